// round 1
// baseline (speedup 1.0000x reference)
#include <cuda_runtime.h>
#include <cuda_bf16.h>
#include <math.h>

#define N_NODES 20000
#define E_MAX   320000
#define E_TOT   (E_MAX + N_NODES)

// ---------------- device scratch (static globals; no runtime alloc) ----------
__device__ float g_h  [N_NODES * 512];          // transformed features (up to 4 heads)
__device__ float g_acc[N_NODES * 512];          // per-head aggregation accumulator
__device__ float g_x0 [N_NODES * 128];          // layer1 out / mlp1 out
__device__ float g_x1 [N_NODES * 128];          // layer2 out
__device__ float g_x2 [N_NODES * 128];          // layer3 out
__device__ float g_as [N_NODES * 4];
__device__ float g_ad [N_NODES * 4];
__device__ float g_max[N_NODES * 4];
__device__ float g_den[N_NODES * 4];
__device__ float g_ex [E_TOT * 4];
__device__ float g_m2 [N_NODES * 64];           // mlp2 out

// ---------------- helpers ----------------------------------------------------
__device__ __forceinline__ void atomicMaxFloat(float* addr, float value) {
    if (value >= 0.f) atomicMax((int*)addr, __float_as_int(value));
    else              atomicMin((unsigned int*)addr, __float_as_uint(value));
}

__global__ void fill_kernel(float* p, float v, int n) {
    int i = blockIdx.x * blockDim.x + threadIdx.x;
    if (i < n) p[i] = v;
}

// ---------------- SGEMM: C[M,N] = A[M,K] @ B[K,N] (+bias, act) ---------------
// act: 0 none, 1 relu, 2 sigmoid
__global__ void sgemm_kernel(const float* __restrict__ A, const float* __restrict__ B,
                             const float* __restrict__ bias, float* __restrict__ C,
                             int M, int N, int K, int act)
{
    const int BM = 64, BN = 64, BK = 16, TM = 4, TN = 4;
    __shared__ float As[BK][BM];
    __shared__ float Bs[BK][BN];

    int tid = threadIdx.x;             // 256 threads
    int tx = tid & 15, ty = tid >> 4;  // 16x16
    int row0 = blockIdx.y * BM + ty * TM;
    int col0 = blockIdx.x * BN + tx * TN;

    float acc[TM][TN];
#pragma unroll
    for (int i = 0; i < TM; i++)
#pragma unroll
        for (int j = 0; j < TN; j++) acc[i][j] = 0.f;

    for (int k0 = 0; k0 < K; k0 += BK) {
        // A tile: BM x BK (64x16), 1024 elems, 4 per thread (contiguous in k)
#pragma unroll
        for (int i = 0; i < 4; i++) {
            int l = tid * 4 + i;
            int a_r = l >> 4, a_c = l & 15;
            int gr = blockIdx.y * BM + a_r;
            As[a_c][a_r] = (gr < M) ? A[(size_t)gr * K + k0 + a_c] : 0.f;
        }
        // B tile: BK x BN (16x64), 1024 elems
#pragma unroll
        for (int i = 0; i < 4; i++) {
            int l = tid * 4 + i;
            int b_r = l >> 6, b_c = l & 63;
            int gc = blockIdx.x * BN + b_c;
            Bs[b_r][b_c] = (gc < N) ? B[(size_t)(k0 + b_r) * N + gc] : 0.f;
        }
        __syncthreads();
#pragma unroll
        for (int kk = 0; kk < BK; kk++) {
            float a[TM], b[TN];
#pragma unroll
            for (int i = 0; i < TM; i++) a[i] = As[kk][ty * TM + i];
#pragma unroll
            for (int j = 0; j < TN; j++) b[j] = Bs[kk][tx * TN + j];
#pragma unroll
            for (int i = 0; i < TM; i++)
#pragma unroll
                for (int j = 0; j < TN; j++) acc[i][j] += a[i] * b[j];
        }
        __syncthreads();
    }

#pragma unroll
    for (int i = 0; i < TM; i++) {
        int r = row0 + i;
        if (r >= M) continue;
#pragma unroll
        for (int j = 0; j < TN; j++) {
            int c = col0 + j;
            if (c >= N) continue;
            float v = acc[i][j] + (bias ? bias[c] : 0.f);
            if (act == 1)      v = fmaxf(v, 0.f);
            else if (act == 2) v = 1.f / (1.f + expf(-v));
            C[(size_t)r * N + c] = v;
        }
    }
}

// ---------------- attention coefficient precompute ---------------------------
// as[n,h] = dot(h[n,h,:], a_src[h,:]) ; ad likewise. One warp per (n,h).
__global__ void alpha_kernel(const float* __restrict__ h, const float* __restrict__ a_src,
                             const float* __restrict__ a_dst, float* __restrict__ as_,
                             float* __restrict__ ad_, int N, int H)
{
    int gw = (blockIdx.x * blockDim.x + threadIdx.x) >> 5;
    int lane = threadIdx.x & 31;
    if (gw >= N * H) return;
    int n = gw / H, hh = gw - n * H;
    const float* hp = h + ((size_t)n * H + hh) * 128;
    const float* sp = a_src + hh * 128;
    const float* dp = a_dst + hh * 128;
    float s = 0.f, d = 0.f;
#pragma unroll
    for (int c = lane; c < 128; c += 32) {
        float v = hp[c];
        s += v * sp[c];
        d += v * dp[c];
    }
#pragma unroll
    for (int o = 16; o; o >>= 1) {
        s += __shfl_xor_sync(0xFFFFFFFFu, s, o);
        d += __shfl_xor_sync(0xFFFFFFFFu, d, o);
    }
    if (lane == 0) { as_[n * H + hh] = s; ad_[n * H + hh] = d; }
}

// ---------------- edge pass 1: segment max ------------------------------------
__global__ void edge_max_kernel(const int* __restrict__ src, const int* __restrict__ dst,
                                int E, int N, int H, const float* __restrict__ as_,
                                const float* __restrict__ ad_, float* __restrict__ nmax)
{
    int i = blockIdx.x * blockDim.x + threadIdx.x;
    int tot = (E + N) * H;
    if (i >= tot) return;
    int e = i / H, hh = i - e * H;
    int s, d;
    if (e < E) { s = src[e]; d = dst[e]; } else { s = d = e - E; }
    float v = as_[s * H + hh] + ad_[d * H + hh];
    v = v > 0.f ? v : 0.2f * v;   // leaky relu 0.2
    atomicMaxFloat(&nmax[d * H + hh], v);
}

// ---------------- edge pass 2: exp + denominator ------------------------------
__global__ void edge_exp_kernel(const int* __restrict__ src, const int* __restrict__ dst,
                                int E, int N, int H, const float* __restrict__ as_,
                                const float* __restrict__ ad_, const float* __restrict__ nmax,
                                float* __restrict__ exbuf, float* __restrict__ den)
{
    int i = blockIdx.x * blockDim.x + threadIdx.x;
    int tot = (E + N) * H;
    if (i >= tot) return;
    int e = i / H, hh = i - e * H;
    int s, d;
    if (e < E) { s = src[e]; d = dst[e]; } else { s = d = e - E; }
    float v = as_[s * H + hh] + ad_[d * H + hh];
    v = v > 0.f ? v : 0.2f * v;
    float ex = expf(v - nmax[d * H + hh]);
    exbuf[i] = ex;
    atomicAdd(&den[d * H + hh], ex);
}

// ---------------- edge pass 3: weighted scatter -------------------------------
// One warp per (edge, head); lanes cover 128 channels via float4.
__global__ void edge_agg_kernel(const int* __restrict__ src, const int* __restrict__ dst,
                                int E, int N, int H, const float* __restrict__ exbuf,
                                const float* __restrict__ den, const float* __restrict__ h,
                                float* __restrict__ acc)
{
    int gw = (blockIdx.x * blockDim.x + threadIdx.x) >> 5;
    int lane = threadIdx.x & 31;
    int tot = (E + N) * H;
    if (gw >= tot) return;
    int e = gw / H, hh = gw - e * H;
    int s, d;
    if (e < E) { s = src[e]; d = dst[e]; } else { s = d = e - E; }
    float alpha = exbuf[gw] / (den[d * H + hh] + 1e-16f);
    const float4* hp = (const float4*)(h + ((size_t)s * H + hh) * 128);
    float* ap = acc + ((size_t)d * H + hh) * 128;
    float4 v = hp[lane];
    atomicAdd(ap + lane * 4 + 0, v.x * alpha);
    atomicAdd(ap + lane * 4 + 1, v.y * alpha);
    atomicAdd(ap + lane * 4 + 2, v.z * alpha);
    atomicAdd(ap + lane * 4 + 3, v.w * alpha);
}

// ---------------- finalize (mean over heads + bias + BN + relu) ---------------
__global__ void finalize_bn_kernel(const float* __restrict__ acc, const float* __restrict__ bias,
                                   const float* __restrict__ g, const float* __restrict__ bb,
                                   const float* __restrict__ m, const float* __restrict__ v,
                                   float* __restrict__ out, int N)
{
    int i = blockIdx.x * blockDim.x + threadIdx.x;
    if (i >= N * 128) return;
    int n = i >> 7, c = i & 127;
    const float* ap = acc + (size_t)n * 512;
    float s = 0.25f * (ap[c] + ap[128 + c] + ap[256 + c] + ap[384 + c]) + bias[c];
    float y = g[c] * (s - m[c]) * rsqrtf(v[c] + 1e-5f) + bb[c];
    out[i] = fmaxf(y, 0.f);
}

// layer-3 finalize: single head, concat => just + bias
__global__ void finalize_b_kernel(const float* __restrict__ acc, const float* __restrict__ bias,
                                  float* __restrict__ out, int N)
{
    int i = blockIdx.x * blockDim.x + threadIdx.x;
    if (i >= N * 128) return;
    int c = i & 127;
    out[i] = acc[i] + bias[c];
}

// ---------------- host-side orchestration -------------------------------------
static void launch_fill(float* p, float v, int n) {
    fill_kernel<<<(n + 255) / 256, 256>>>(p, v, n);
}

static void launch_gemm(const float* A, const float* B, const float* bias, float* C,
                        int M, int N, int K, int act) {
    dim3 grid((N + 63) / 64, (M + 63) / 64);
    sgemm_kernel<<<grid, 256>>>(A, B, bias, C, M, N, K, act);
}

struct Scratch {
    float *h, *acc, *x0, *x1, *x2, *as, *ad, *mx, *den, *ex, *m2;
};

static void run_gat(const float* xin, int in_dim, const float* W, const float* a_src,
                    const float* a_dst, const int* src, const int* dst, int E, int N,
                    int H, const Scratch& S)
{
    // 1. h = xin @ W
    launch_gemm(xin, W, nullptr, S.h, N, H * 128, in_dim, 0);
    // 2. per-node attention coefficients
    {
        int warps = N * H;
        alpha_kernel<<<(warps * 32 + 255) / 256, 256>>>(S.h, a_src, a_dst, S.as, S.ad, N, H);
    }
    // 3. reset reductions
    launch_fill(S.mx, -INFINITY, N * H);
    launch_fill(S.den, 0.f, N * H);
    launch_fill(S.acc, 0.f, N * H * 128);
    // 4-6. edge passes
    int tot = (E + N) * H;
    edge_max_kernel<<<(tot + 255) / 256, 256>>>(src, dst, E, N, H, S.as, S.ad, S.mx);
    edge_exp_kernel<<<(tot + 255) / 256, 256>>>(src, dst, E, N, H, S.as, S.ad, S.mx, S.ex, S.den);
    {
        long long threads = (long long)tot * 32;
        edge_agg_kernel<<<(int)((threads + 255) / 256), 256>>>(src, dst, E, N, H, S.ex, S.den, S.h, S.acc);
    }
}

extern "C" void kernel_launch(void* const* d_in, const int* in_sizes, int n_in,
                              void* d_out, int out_size)
{
    const float* x   = (const float*)d_in[0];
    const int*   ei  = (const int*)  d_in[1];
    const float* W1  = (const float*)d_in[2];
    const float* as1 = (const float*)d_in[3];
    const float* ad1 = (const float*)d_in[4];
    const float* b1  = (const float*)d_in[5];
    const float* W2  = (const float*)d_in[6];
    const float* as2 = (const float*)d_in[7];
    const float* ad2 = (const float*)d_in[8];
    const float* b2  = (const float*)d_in[9];
    const float* W3  = (const float*)d_in[10];
    const float* as3 = (const float*)d_in[11];
    const float* ad3 = (const float*)d_in[12];
    const float* b3  = (const float*)d_in[13];
    const float* bn1g = (const float*)d_in[14];
    const float* bn1b = (const float*)d_in[15];
    const float* bn1m = (const float*)d_in[16];
    const float* bn1v = (const float*)d_in[17];
    const float* bn2g = (const float*)d_in[18];
    const float* bn2b = (const float*)d_in[19];
    const float* bn2m = (const float*)d_in[20];
    const float* bn2v = (const float*)d_in[21];
    const float* l1w = (const float*)d_in[22];
    const float* l1b = (const float*)d_in[23];
    const float* l2w = (const float*)d_in[24];
    const float* l2b = (const float*)d_in[25];
    const float* l3w = (const float*)d_in[26];
    const float* l3b = (const float*)d_in[27];

    const int N = in_sizes[0] / 256;       // 20000
    const int E = in_sizes[1] / 2;         // 320000
    const int* src = ei;
    const int* dst = ei + E;

    Scratch S;
    cudaGetSymbolAddress((void**)&S.h,   g_h);
    cudaGetSymbolAddress((void**)&S.acc, g_acc);
    cudaGetSymbolAddress((void**)&S.x0,  g_x0);
    cudaGetSymbolAddress((void**)&S.x1,  g_x1);
    cudaGetSymbolAddress((void**)&S.x2,  g_x2);
    cudaGetSymbolAddress((void**)&S.as,  g_as);
    cudaGetSymbolAddress((void**)&S.ad,  g_ad);
    cudaGetSymbolAddress((void**)&S.mx,  g_max);
    cudaGetSymbolAddress((void**)&S.den, g_den);
    cudaGetSymbolAddress((void**)&S.ex,  g_ex);
    cudaGetSymbolAddress((void**)&S.m2,  g_m2);

    // ---- GAT layer 1 (heads=4, mean) + BN1 + relu ----
    run_gat(x, 256, W1, as1, ad1, src, dst, E, N, 4, S);
    finalize_bn_kernel<<<(N * 128 + 255) / 256, 256>>>(S.acc, b1, bn1g, bn1b, bn1m, bn1v, S.x0, N);

    // ---- GAT layer 2 (heads=4, mean) + BN2 + relu ----
    run_gat(S.x0, 128, W2, as2, ad2, src, dst, E, N, 4, S);
    finalize_bn_kernel<<<(N * 128 + 255) / 256, 256>>>(S.acc, b2, bn2g, bn2b, bn2m, bn2v, S.x1, N);

    // ---- GAT layer 3 (heads=1, concat) ----
    run_gat(S.x1, 128, W3, as3, ad3, src, dst, E, N, 1, S);
    finalize_b_kernel<<<(N * 128 + 255) / 256, 256>>>(S.acc, b3, S.x2, N);

    // ---- classifier MLP ----
    launch_gemm(S.x2, l1w, l1b, S.x0, N, 128, 128, 1);   // relu
    launch_gemm(S.x0, l2w, l2b, S.m2, N, 64, 128, 1);    // relu
    launch_gemm(S.m2, l3w, l3b, (float*)d_out, N, 64, 64, 2); // sigmoid
}

// round 3
// speedup vs baseline: 2.2694x; 2.2694x over previous
#include <cuda_runtime.h>
#include <cuda_bf16.h>
#include <math.h>

#define N_NODES 20000
#define E_MAX   320000
#define E_TOT   (E_MAX + N_NODES)

// ---------------- device scratch (static globals; no runtime alloc) ----------
__device__ float g_h  [N_NODES * 512];          // transformed features (up to 4 heads)
__device__ float g_acc[N_NODES * 512];          // per-head aggregation accumulator
__device__ float g_x0 [N_NODES * 128];
__device__ float g_x1 [N_NODES * 128];
__device__ float g_x2 [N_NODES * 128];
__device__ float g_as [N_NODES * 4];
__device__ float g_ad [N_NODES * 4];
__device__ float g_max[N_NODES * 4];
__device__ float g_den[N_NODES * 4];
__device__ float g_ex [E_TOT * 4];
__device__ float g_m2 [N_NODES * 64];

// ---------------- helpers ----------------------------------------------------
__device__ __forceinline__ void atomicMaxFloat(float* addr, float value) {
    if (value >= 0.f) atomicMax((int*)addr, __float_as_int(value));
    else              atomicMin((unsigned int*)addr, __float_as_uint(value));
}

__global__ void fill_kernel(float* p, float v, int n) {
    int i = blockIdx.x * blockDim.x + threadIdx.x;
    if (i < n) p[i] = v;
}

// ---------------- SGEMM: C[M,N] = A[M,K] @ B[K,N] (+bias, act) ---------------
// 128x128x8 tile, 256 threads, 8x8 per thread, float4 global+shared accesses.
// Requires K % 8 == 0 and N % 4 == 0 (true here: K in {256,128,64}, N in {512,128,64}).
// act: 0 none, 1 relu, 2 sigmoid
__global__ __launch_bounds__(256, 2)
void sgemm_kernel(const float* __restrict__ A, const float* __restrict__ B,
                  const float* __restrict__ bias, float* __restrict__ C,
                  int M, int N, int K, int act)
{
    const int BM = 128, BN = 128, BK = 8;
    __shared__ float As[BK][BM];
    __shared__ float Bs[BK][BN];

    int tid = threadIdx.x;               // 256 threads
    int tx = tid & 15, ty = tid >> 4;    // 16x16 thread grid, 8x8 each
    int bm = blockIdx.y * BM, bn = blockIdx.x * BN;

    // global-load assignments (one float4 each for A and B per k-tile)
    int a_row = tid >> 1;                // 0..127
    int a_col = (tid & 1) << 2;          // 0 or 4
    int b_row = tid >> 5;                // 0..7
    int b_col = (tid & 31) << 2;         // 0..124

    float acc[8][8];
#pragma unroll
    for (int i = 0; i < 8; i++)
#pragma unroll
        for (int j = 0; j < 8; j++) acc[i][j] = 0.f;

    const bool a_ok = (bm + a_row) < M;
    const bool b_ok = (bn + b_col) < N;

    for (int k0 = 0; k0 < K; k0 += BK) {
        float4 av = make_float4(0.f, 0.f, 0.f, 0.f);
        if (a_ok) av = *(const float4*)(A + (size_t)(bm + a_row) * K + k0 + a_col);
        As[a_col + 0][a_row] = av.x;
        As[a_col + 1][a_row] = av.y;
        As[a_col + 2][a_row] = av.z;
        As[a_col + 3][a_row] = av.w;

        float4 bv = make_float4(0.f, 0.f, 0.f, 0.f);
        if (b_ok) bv = *(const float4*)(B + (size_t)(k0 + b_row) * N + bn + b_col);
        *(float4*)&Bs[b_row][b_col] = bv;
        __syncthreads();

#pragma unroll
        for (int kk = 0; kk < BK; kk++) {
            float a[8], b[8];
            *(float4*)&a[0] = *(float4*)&As[kk][ty * 8];
            *(float4*)&a[4] = *(float4*)&As[kk][ty * 8 + 4];
            *(float4*)&b[0] = *(float4*)&Bs[kk][tx * 8];
            *(float4*)&b[4] = *(float4*)&Bs[kk][tx * 8 + 4];
#pragma unroll
            for (int i = 0; i < 8; i++)
#pragma unroll
                for (int j = 0; j < 8; j++) acc[i][j] += a[i] * b[j];
        }
        __syncthreads();
    }

#pragma unroll
    for (int i = 0; i < 8; i++) {
        int r = bm + ty * 8 + i;
        if (r >= M) continue;
#pragma unroll
        for (int j = 0; j < 8; j++) {
            int c = bn + tx * 8 + j;
            if (c >= N) continue;
            float v = acc[i][j] + (bias ? bias[c] : 0.f);
            if (act == 1)      v = fmaxf(v, 0.f);
            else if (act == 2) v = 1.f / (1.f + expf(-v));
            C[(size_t)r * N + c] = v;
        }
    }
}

// ---------------- attention coefficient precompute ---------------------------
__global__ void alpha_kernel(const float* __restrict__ h, const float* __restrict__ a_src,
                             const float* __restrict__ a_dst, float* __restrict__ as_,
                             float* __restrict__ ad_, int N, int H)
{
    int gw = (blockIdx.x * blockDim.x + threadIdx.x) >> 5;
    int lane = threadIdx.x & 31;
    if (gw >= N * H) return;
    int n = gw / H, hh = gw - n * H;
    const float4* hp = (const float4*)(h + ((size_t)n * H + hh) * 128);
    const float4* sp = (const float4*)(a_src + hh * 128);
    const float4* dp = (const float4*)(a_dst + hh * 128);
    float4 v = hp[lane], sv = sp[lane], dv = dp[lane];
    float s = v.x * sv.x + v.y * sv.y + v.z * sv.z + v.w * sv.w;
    float d = v.x * dv.x + v.y * dv.y + v.z * dv.z + v.w * dv.w;
#pragma unroll
    for (int o = 16; o; o >>= 1) {
        s += __shfl_xor_sync(0xFFFFFFFFu, s, o);
        d += __shfl_xor_sync(0xFFFFFFFFu, d, o);
    }
    if (lane == 0) { as_[n * H + hh] = s; ad_[n * H + hh] = d; }
}

// ---------------- edge pass 1: segment max ------------------------------------
__global__ void edge_max_kernel(const int* __restrict__ src, const int* __restrict__ dst,
                                int E, int N, int H, const float* __restrict__ as_,
                                const float* __restrict__ ad_, float* __restrict__ nmax)
{
    int i = blockIdx.x * blockDim.x + threadIdx.x;
    int tot = (E + N) * H;
    if (i >= tot) return;
    int e = i / H, hh = i - e * H;
    int s, d;
    if (e < E) { s = src[e]; d = dst[e]; } else { s = d = e - E; }
    float v = as_[s * H + hh] + ad_[d * H + hh];
    v = v > 0.f ? v : 0.2f * v;   // leaky relu 0.2
    atomicMaxFloat(&nmax[d * H + hh], v);
}

// ---------------- edge pass 2: exp + denominator ------------------------------
__global__ void edge_exp_kernel(const int* __restrict__ src, const int* __restrict__ dst,
                                int E, int N, int H, const float* __restrict__ as_,
                                const float* __restrict__ ad_, const float* __restrict__ nmax,
                                float* __restrict__ exbuf, float* __restrict__ den)
{
    int i = blockIdx.x * blockDim.x + threadIdx.x;
    int tot = (E + N) * H;
    if (i >= tot) return;
    int e = i / H, hh = i - e * H;
    int s, d;
    if (e < E) { s = src[e]; d = dst[e]; } else { s = d = e - E; }
    float v = as_[s * H + hh] + ad_[d * H + hh];
    v = v > 0.f ? v : 0.2f * v;
    float ex = expf(v - nmax[d * H + hh]);
    exbuf[i] = ex;
    atomicAdd(&den[d * H + hh], ex);
}

// ---------------- edge pass 3: weighted scatter -------------------------------
// One warp per (edge, head); lanes cover 128 channels via float4; vector red.
__global__ void edge_agg_kernel(const int* __restrict__ src, const int* __restrict__ dst,
                                int E, int N, int H, const float* __restrict__ exbuf,
                                const float* __restrict__ den, const float* __restrict__ h,
                                float* __restrict__ acc)
{
    int gw = (blockIdx.x * blockDim.x + threadIdx.x) >> 5;
    int lane = threadIdx.x & 31;
    int tot = (E + N) * H;
    if (gw >= tot) return;
    int e = gw / H, hh = gw - e * H;
    int s, d;
    if (e < E) { s = src[e]; d = dst[e]; } else { s = d = e - E; }
    float alpha = exbuf[gw] / (den[d * H + hh] + 1e-16f);
    const float4* hp = (const float4*)(h + ((size_t)s * H + hh) * 128);
    float* ap = acc + ((size_t)d * H + hh) * 128 + lane * 4;
    float4 v = hp[lane];
    asm volatile("red.global.add.v4.f32 [%0], {%1, %2, %3, %4};"
                 :: "l"(ap), "f"(v.x * alpha), "f"(v.y * alpha),
                    "f"(v.z * alpha), "f"(v.w * alpha)
                 : "memory");
}

// ---------------- finalize (mean over heads + bias + BN + relu) ---------------
__global__ void finalize_bn_kernel(const float* __restrict__ acc, const float* __restrict__ bias,
                                   const float* __restrict__ g, const float* __restrict__ bb,
                                   const float* __restrict__ m, const float* __restrict__ v,
                                   float* __restrict__ out, int N)
{
    int i = blockIdx.x * blockDim.x + threadIdx.x;
    if (i >= N * 128) return;
    int n = i >> 7, c = i & 127;
    const float* ap = acc + (size_t)n * 512;
    float s = 0.25f * (ap[c] + ap[128 + c] + ap[256 + c] + ap[384 + c]) + bias[c];
    float y = g[c] * (s - m[c]) * rsqrtf(v[c] + 1e-5f) + bb[c];
    out[i] = fmaxf(y, 0.f);
}

__global__ void finalize_b_kernel(const float* __restrict__ acc, const float* __restrict__ bias,
                                  float* __restrict__ out, int N)
{
    int i = blockIdx.x * blockDim.x + threadIdx.x;
    if (i >= N * 128) return;
    int c = i & 127;
    out[i] = acc[i] + bias[c];
}

// ---------------- host-side orchestration -------------------------------------
static void launch_fill(float* p, float v, int n) {
    fill_kernel<<<(n + 255) / 256, 256>>>(p, v, n);
}

static void launch_gemm(const float* A, const float* B, const float* bias, float* C,
                        int M, int N, int K, int act) {
    dim3 grid((N + 127) / 128, (M + 127) / 128);
    sgemm_kernel<<<grid, 256>>>(A, B, bias, C, M, N, K, act);
}

struct Scratch {
    float *h, *acc, *x0, *x1, *x2, *as, *ad, *mx, *den, *ex, *m2;
};

static void run_gat(const float* xin, int in_dim, const float* W, const float* a_src,
                    const float* a_dst, const int* src, const int* dst, int E, int N,
                    int H, const Scratch& S)
{
    launch_gemm(xin, W, nullptr, S.h, N, H * 128, in_dim, 0);
    {
        int warps = N * H;
        alpha_kernel<<<(warps * 32 + 255) / 256, 256>>>(S.h, a_src, a_dst, S.as, S.ad, N, H);
    }
    launch_fill(S.mx, -INFINITY, N * H);
    launch_fill(S.den, 0.f, N * H);
    launch_fill(S.acc, 0.f, N * H * 128);
    int tot = (E + N) * H;
    edge_max_kernel<<<(tot + 255) / 256, 256>>>(src, dst, E, N, H, S.as, S.ad, S.mx);
    edge_exp_kernel<<<(tot + 255) / 256, 256>>>(src, dst, E, N, H, S.as, S.ad, S.mx, S.ex, S.den);
    {
        long long threads = (long long)tot * 32;
        edge_agg_kernel<<<(int)((threads + 255) / 256), 256>>>(src, dst, E, N, H, S.ex, S.den, S.h, S.acc);
    }
}

extern "C" void kernel_launch(void* const* d_in, const int* in_sizes, int n_in,
                              void* d_out, int out_size)
{
    const float* x   = (const float*)d_in[0];
    const int*   ei  = (const int*)  d_in[1];
    const float* W1  = (const float*)d_in[2];
    const float* as1 = (const float*)d_in[3];
    const float* ad1 = (const float*)d_in[4];
    const float* b1  = (const float*)d_in[5];
    const float* W2  = (const float*)d_in[6];
    const float* as2 = (const float*)d_in[7];
    const float* ad2 = (const float*)d_in[8];
    const float* b2  = (const float*)d_in[9];
    const float* W3  = (const float*)d_in[10];
    const float* as3 = (const float*)d_in[11];
    const float* ad3 = (const float*)d_in[12];
    const float* b3  = (const float*)d_in[13];
    const float* bn1g = (const float*)d_in[14];
    const float* bn1b = (const float*)d_in[15];
    const float* bn1m = (const float*)d_in[16];
    const float* bn1v = (const float*)d_in[17];
    const float* bn2g = (const float*)d_in[18];
    const float* bn2b = (const float*)d_in[19];
    const float* bn2m = (const float*)d_in[20];
    const float* bn2v = (const float*)d_in[21];
    const float* l1w = (const float*)d_in[22];
    const float* l1b = (const float*)d_in[23];
    const float* l2w = (const float*)d_in[24];
    const float* l2b = (const float*)d_in[25];
    const float* l3w = (const float*)d_in[26];
    const float* l3b = (const float*)d_in[27];

    const int N = in_sizes[0] / 256;       // 20000
    const int E = in_sizes[1] / 2;         // 320000
    const int* src = ei;
    const int* dst = ei + E;

    Scratch S;
    cudaGetSymbolAddress((void**)&S.h,   g_h);
    cudaGetSymbolAddress((void**)&S.acc, g_acc);
    cudaGetSymbolAddress((void**)&S.x0,  g_x0);
    cudaGetSymbolAddress((void**)&S.x1,  g_x1);
    cudaGetSymbolAddress((void**)&S.x2,  g_x2);
    cudaGetSymbolAddress((void**)&S.as,  g_as);
    cudaGetSymbolAddress((void**)&S.ad,  g_ad);
    cudaGetSymbolAddress((void**)&S.mx,  g_max);
    cudaGetSymbolAddress((void**)&S.den, g_den);
    cudaGetSymbolAddress((void**)&S.ex,  g_ex);
    cudaGetSymbolAddress((void**)&S.m2,  g_m2);

    // ---- GAT layer 1 (heads=4, mean) + BN1 + relu ----
    run_gat(x, 256, W1, as1, ad1, src, dst, E, N, 4, S);
    finalize_bn_kernel<<<(N * 128 + 255) / 256, 256>>>(S.acc, b1, bn1g, bn1b, bn1m, bn1v, S.x0, N);

    // ---- GAT layer 2 (heads=4, mean) + BN2 + relu ----
    run_gat(S.x0, 128, W2, as2, ad2, src, dst, E, N, 4, S);
    finalize_bn_kernel<<<(N * 128 + 255) / 256, 256>>>(S.acc, b2, bn2g, bn2b, bn2m, bn2v, S.x1, N);

    // ---- GAT layer 3 (heads=1, concat) ----
    run_gat(S.x1, 128, W3, as3, ad3, src, dst, E, N, 1, S);
    finalize_b_kernel<<<(N * 128 + 255) / 256, 256>>>(S.acc, b3, S.x2, N);

    // ---- classifier MLP ----
    launch_gemm(S.x2, l1w, l1b, S.x0, N, 128, 128, 1);   // relu
    launch_gemm(S.x0, l2w, l2b, S.m2, N, 64, 128, 1);    // relu
    launch_gemm(S.m2, l3w, l3b, (float*)d_out, N, 64, 64, 2); // sigmoid
}

// round 4
// speedup vs baseline: 3.8282x; 1.6869x over previous
#include <cuda_runtime.h>
#include <cuda_bf16.h>
#include <math.h>

#define N_NODES 20000
#define E_MAX   320000

// ---------------- device scratch ----------------------------------------------
__device__ float g_h  [N_NODES * 512];          // transformed features (up to 4 heads)
__device__ float g_x0 [N_NODES * 128];
__device__ float g_x1 [N_NODES * 128];
__device__ float g_x2 [N_NODES * 128];
__device__ float g_as [N_NODES * 4];
__device__ float g_ad [N_NODES * 4];
__device__ float g_m2 [N_NODES * 64];
__device__ int   g_deg[N_NODES];
__device__ int   g_off[N_NODES + 1];
__device__ int   g_cur[N_NODES];
__device__ int   g_csr[E_MAX];

// ---------------- packed fp32 FMA (Blackwell FFMA2, PTX-only path) ------------
__device__ __forceinline__ float2 ffma2(float2 a, float2 b, float2 c) {
    unsigned long long A = *reinterpret_cast<unsigned long long*>(&a);
    unsigned long long B = *reinterpret_cast<unsigned long long*>(&b);
    unsigned long long C = *reinterpret_cast<unsigned long long*>(&c);
    unsigned long long D;
    asm("fma.rn.f32x2 %0, %1, %2, %3;" : "=l"(D) : "l"(A), "l"(B), "l"(C));
    return *reinterpret_cast<float2*>(&D);
}

// ---------------- CSR build ----------------------------------------------------
__global__ void zero_deg_kernel(int N) {
    int i = blockIdx.x * blockDim.x + threadIdx.x;
    if (i < N) g_deg[i] = 0;
}
__global__ void hist_kernel(const int* __restrict__ dst, int E) {
    int i = blockIdx.x * blockDim.x + threadIdx.x;
    if (i < E) atomicAdd(&g_deg[dst[i]], 1);
}
__global__ void scan_kernel(int N) {   // single block, 1024 threads
    __shared__ int sh[1024];
    int tid = threadIdx.x;
    int per = (N + 1023) >> 10;
    int base = tid * per;
    int sum = 0;
    for (int i = 0; i < per; i++) { int idx = base + i; if (idx < N) sum += g_deg[idx]; }
    sh[tid] = sum;
    __syncthreads();
    for (int off = 1; off < 1024; off <<= 1) {
        int v = (tid >= off) ? sh[tid - off] : 0;
        __syncthreads();
        sh[tid] += v;
        __syncthreads();
    }
    int run = tid ? sh[tid - 1] : 0;
    for (int i = 0; i < per; i++) {
        int idx = base + i;
        if (idx < N) { g_off[idx] = run; g_cur[idx] = run; run += g_deg[idx]; }
    }
    if (tid == 1023) g_off[N] = sh[1023];
}
__global__ void scatter_kernel(const int* __restrict__ src, const int* __restrict__ dst, int E) {
    int i = blockIdx.x * blockDim.x + threadIdx.x;
    if (i < E) {
        int p = atomicAdd(&g_cur[dst[i]], 1);
        g_csr[p] = src[i];
    }
}

// ---------------- SGEMM (128x128x8, f32x2 packed inner product) ---------------
// act: 0 none, 1 relu, 2 sigmoid
__global__ __launch_bounds__(256, 2)
void sgemm_kernel(const float* __restrict__ A, const float* __restrict__ B,
                  const float* __restrict__ bias, float* __restrict__ C,
                  int M, int N, int K, int act)
{
    const int BM = 128, BN = 128, BK = 8;
    __shared__ float As[BK][BM];
    __shared__ float Bs[BK][BN];

    int tid = threadIdx.x;
    int tx = tid & 15, ty = tid >> 4;
    int bm = blockIdx.y * BM, bn = blockIdx.x * BN;

    int a_row = tid >> 1, a_col = (tid & 1) << 2;
    int b_row = tid >> 5, b_col = (tid & 31) << 2;

    float2 acc[8][4];
#pragma unroll
    for (int i = 0; i < 8; i++)
#pragma unroll
        for (int j = 0; j < 4; j++) acc[i][j] = make_float2(0.f, 0.f);

    const bool a_ok = (bm + a_row) < M;
    const bool b_ok = (bn + b_col) < N;

    for (int k0 = 0; k0 < K; k0 += BK) {
        float4 av = make_float4(0.f, 0.f, 0.f, 0.f);
        if (a_ok) av = *(const float4*)(A + (size_t)(bm + a_row) * K + k0 + a_col);
        As[a_col + 0][a_row] = av.x;
        As[a_col + 1][a_row] = av.y;
        As[a_col + 2][a_row] = av.z;
        As[a_col + 3][a_row] = av.w;

        float4 bv = make_float4(0.f, 0.f, 0.f, 0.f);
        if (b_ok) bv = *(const float4*)(B + (size_t)(k0 + b_row) * N + bn + b_col);
        *(float4*)&Bs[b_row][b_col] = bv;
        __syncthreads();

#pragma unroll
        for (int kk = 0; kk < BK; kk++) {
            float a[8];
            *(float4*)&a[0] = *(float4*)&As[kk][ty * 8];
            *(float4*)&a[4] = *(float4*)&As[kk][ty * 8 + 4];
            float4 b0 = *(float4*)&Bs[kk][tx * 8];
            float4 b1 = *(float4*)&Bs[kk][tx * 8 + 4];
            float2 b2[4];
            b2[0] = make_float2(b0.x, b0.y);
            b2[1] = make_float2(b0.z, b0.w);
            b2[2] = make_float2(b1.x, b1.y);
            b2[3] = make_float2(b1.z, b1.w);
#pragma unroll
            for (int i = 0; i < 8; i++) {
                float2 ap = make_float2(a[i], a[i]);
#pragma unroll
                for (int j = 0; j < 4; j++) acc[i][j] = ffma2(ap, b2[j], acc[i][j]);
            }
        }
        __syncthreads();
    }

#pragma unroll
    for (int i = 0; i < 8; i++) {
        int r = bm + ty * 8 + i;
        if (r >= M) continue;
#pragma unroll
        for (int j = 0; j < 4; j++) {
#pragma unroll
            for (int p = 0; p < 2; p++) {
                int c = bn + tx * 8 + j * 2 + p;
                if (c >= N) continue;
                float v = (p ? acc[i][j].y : acc[i][j].x) + (bias ? bias[c] : 0.f);
                if (act == 1)      v = fmaxf(v, 0.f);
                else if (act == 2) v = 1.f / (1.f + expf(-v));
                C[(size_t)r * N + c] = v;
            }
        }
    }
}

// ---------------- attention coefficient precompute ----------------------------
__global__ void alpha_kernel(const float* __restrict__ h, const float* __restrict__ a_src,
                             const float* __restrict__ a_dst, float* __restrict__ as_,
                             float* __restrict__ ad_, int N, int H)
{
    int gw = (blockIdx.x * blockDim.x + threadIdx.x) >> 5;
    int lane = threadIdx.x & 31;
    if (gw >= N * H) return;
    int n = gw / H, hh = gw - n * H;
    const float4* hp = (const float4*)(h + ((size_t)n * H + hh) * 128);
    const float4* sp = (const float4*)(a_src + hh * 128);
    const float4* dp = (const float4*)(a_dst + hh * 128);
    float4 v = hp[lane], sv = sp[lane], dv = dp[lane];
    float s = v.x * sv.x + v.y * sv.y + v.z * sv.z + v.w * sv.w;
    float d = v.x * dv.x + v.y * dv.y + v.z * dv.z + v.w * dv.w;
#pragma unroll
    for (int o = 16; o; o >>= 1) {
        s += __shfl_xor_sync(0xFFFFFFFFu, s, o);
        d += __shfl_xor_sync(0xFFFFFFFFu, d, o);
    }
    if (lane == 0) { as_[n * H + hh] = s; ad_[n * H + hh] = d; }
}

// ---------------- fused GAT aggregation (one warp per dst node) ----------------
// Computes, per destination node, the full softmax attention aggregation over
// its CSR in-edge list plus the self loop, for all H heads, in registers.
// No max-shift (softmax shift invariance; logits are O(10)). Epilogue applies
// head-mean + bias + optional BN + relu (DO_BN), or bias only.
template<int H, bool DO_BN>
__global__ void gat_agg_kernel(const float* __restrict__ h,
                               const float* __restrict__ as_, const float* __restrict__ ad_,
                               const float* __restrict__ bias,
                               const float* __restrict__ bg, const float* __restrict__ bb,
                               const float* __restrict__ bm_, const float* __restrict__ bv,
                               float* __restrict__ out, int N)
{
    int d = (blockIdx.x * blockDim.x + threadIdx.x) >> 5;
    int lane = threadIdx.x & 31;
    if (d >= N) return;

    // destination-side coefficients
    float asd[H], add[H];
    if (H == 4) {
        float4 t = ((const float4*)as_)[d];
        asd[0] = t.x; asd[1] = t.y; asd[2] = t.z; asd[3] = t.w;
        t = ((const float4*)ad_)[d];
        add[0] = t.x; add[1] = t.y; add[2] = t.z; add[3] = t.w;
    } else {
        asd[0] = as_[d]; add[0] = ad_[d];
    }

    float acc[H][4];
    float denl[H];
#pragma unroll
    for (int k = 0; k < H; k++) {
        denl[k] = 0.f;
#pragma unroll
        for (int c = 0; c < 4; c++) acc[k][c] = 0.f;
    }

    int r0 = g_off[d], r1 = g_off[d + 1];
    for (int base = r0; base < r1; base += 32) {
        int e = base + lane;
        int s = 0;
        float ex[H];
        if (e < r1) {
            s = g_csr[e];
            float av[H];
            if (H == 4) {
                float4 t = ((const float4*)as_)[s];
                av[0] = t.x; av[1] = t.y; av[2] = t.z; av[3] = t.w;
            } else av[0] = as_[s];
#pragma unroll
            for (int k = 0; k < H; k++) {
                float v = av[k] + add[k];
                v = v > 0.f ? v : 0.2f * v;
                ex[k] = expf(v);
                denl[k] += ex[k];
            }
        } else {
#pragma unroll
            for (int k = 0; k < H; k++) ex[k] = 0.f;
        }
        int cnt = min(32, r1 - base);
        for (int j = 0; j < cnt; j++) {
            int sj = __shfl_sync(0xFFFFFFFFu, s, j);
            const float4* hp = (const float4*)(h + (size_t)sj * (H * 128));
#pragma unroll
            for (int k = 0; k < H; k++) {
                float exj = __shfl_sync(0xFFFFFFFFu, ex[k], j);
                float4 hv = hp[k * 32 + lane];
                acc[k][0] += exj * hv.x;
                acc[k][1] += exj * hv.y;
                acc[k][2] += exj * hv.z;
                acc[k][3] += exj * hv.w;
            }
        }
    }

    // self loop + denominator reduction
    const float4* hpd = (const float4*)(h + (size_t)d * (H * 128));
#pragma unroll
    for (int k = 0; k < H; k++) {
        float v = asd[k] + add[k];
        v = v > 0.f ? v : 0.2f * v;
        float exs = expf(v);
        float4 hv = hpd[k * 32 + lane];
        acc[k][0] += exs * hv.x;
        acc[k][1] += exs * hv.y;
        acc[k][2] += exs * hv.z;
        acc[k][3] += exs * hv.w;
        float dk = denl[k];
#pragma unroll
        for (int o = 16; o; o >>= 1) dk += __shfl_xor_sync(0xFFFFFFFFu, dk, o);
        denl[k] = dk + exs;
    }

    // combine heads
    float v0 = 0.f, v1 = 0.f, v2 = 0.f, v3 = 0.f;
#pragma unroll
    for (int k = 0; k < H; k++) {
        float r = 1.f / (denl[k] + 1e-16f);
        v0 += acc[k][0] * r;
        v1 += acc[k][1] * r;
        v2 += acc[k][2] * r;
        v3 += acc[k][3] * r;
    }
    if (H == 4) { v0 *= 0.25f; v1 *= 0.25f; v2 *= 0.25f; v3 *= 0.25f; }

    int c0 = lane * 4;
    float4 bz = *(const float4*)(bias + c0);
    v0 += bz.x; v1 += bz.y; v2 += bz.z; v3 += bz.w;

    float4 o4;
    if (DO_BN) {
        float4 gg = *(const float4*)(bg + c0);
        float4 bb4 = *(const float4*)(bb + c0);
        float4 mm = *(const float4*)(bm_ + c0);
        float4 vv = *(const float4*)(bv + c0);
        o4.x = fmaxf(gg.x * (v0 - mm.x) * rsqrtf(vv.x + 1e-5f) + bb4.x, 0.f);
        o4.y = fmaxf(gg.y * (v1 - mm.y) * rsqrtf(vv.y + 1e-5f) + bb4.y, 0.f);
        o4.z = fmaxf(gg.z * (v2 - mm.z) * rsqrtf(vv.z + 1e-5f) + bb4.z, 0.f);
        o4.w = fmaxf(gg.w * (v3 - mm.w) * rsqrtf(vv.w + 1e-5f) + bb4.w, 0.f);
    } else {
        o4 = make_float4(v0, v1, v2, v3);
    }
    *(float4*)(out + (size_t)d * 128 + c0) = o4;
}

// ---------------- host-side orchestration -------------------------------------
static void launch_gemm(const float* A, const float* B, const float* bias, float* C,
                        int M, int N, int K, int act) {
    dim3 grid((N + 127) / 128, (M + 127) / 128);
    sgemm_kernel<<<grid, 256>>>(A, B, bias, C, M, N, K, act);
}

extern "C" void kernel_launch(void* const* d_in, const int* in_sizes, int n_in,
                              void* d_out, int out_size)
{
    const float* x   = (const float*)d_in[0];
    const int*   ei  = (const int*)  d_in[1];
    const float* W1  = (const float*)d_in[2];
    const float* as1 = (const float*)d_in[3];
    const float* ad1 = (const float*)d_in[4];
    const float* b1  = (const float*)d_in[5];
    const float* W2  = (const float*)d_in[6];
    const float* as2 = (const float*)d_in[7];
    const float* ad2 = (const float*)d_in[8];
    const float* b2  = (const float*)d_in[9];
    const float* W3  = (const float*)d_in[10];
    const float* as3 = (const float*)d_in[11];
    const float* ad3 = (const float*)d_in[12];
    const float* b3  = (const float*)d_in[13];
    const float* bn1g = (const float*)d_in[14];
    const float* bn1b = (const float*)d_in[15];
    const float* bn1m = (const float*)d_in[16];
    const float* bn1v = (const float*)d_in[17];
    const float* bn2g = (const float*)d_in[18];
    const float* bn2b = (const float*)d_in[19];
    const float* bn2m = (const float*)d_in[20];
    const float* bn2v = (const float*)d_in[21];
    const float* l1w = (const float*)d_in[22];
    const float* l1b = (const float*)d_in[23];
    const float* l2w = (const float*)d_in[24];
    const float* l2b = (const float*)d_in[25];
    const float* l3w = (const float*)d_in[26];
    const float* l3b = (const float*)d_in[27];

    const int N = in_sizes[0] / 256;       // 20000
    const int E = in_sizes[1] / 2;         // 320000
    const int* src = ei;
    const int* dst = ei + E;

    float *h, *x0, *x1, *x2, *as_, *ad_, *m2;
    cudaGetSymbolAddress((void**)&h,   g_h);
    cudaGetSymbolAddress((void**)&x0,  g_x0);
    cudaGetSymbolAddress((void**)&x1,  g_x1);
    cudaGetSymbolAddress((void**)&x2,  g_x2);
    cudaGetSymbolAddress((void**)&as_, g_as);
    cudaGetSymbolAddress((void**)&ad_, g_ad);
    cudaGetSymbolAddress((void**)&m2,  g_m2);

    // ---- CSR build (once; dst identical for all 3 layers) ----
    zero_deg_kernel<<<(N + 255) / 256, 256>>>(N);
    hist_kernel<<<(E + 255) / 256, 256>>>(dst, E);
    scan_kernel<<<1, 1024>>>(N);
    scatter_kernel<<<(E + 255) / 256, 256>>>(src, dst, E);

    int agg_blocks = (N * 32 + 255) / 256;

    // ---- GAT layer 1 (heads=4, mean) + BN1 + relu ----
    launch_gemm(x, W1, nullptr, h, N, 512, 256, 0);
    alpha_kernel<<<(N * 4 * 32 + 255) / 256, 256>>>(h, as1, ad1, as_, ad_, N, 4);
    gat_agg_kernel<4, true><<<agg_blocks, 256>>>(h, as_, ad_, b1, bn1g, bn1b, bn1m, bn1v, x0, N);

    // ---- GAT layer 2 (heads=4, mean) + BN2 + relu ----
    launch_gemm(x0, W2, nullptr, h, N, 512, 128, 0);
    alpha_kernel<<<(N * 4 * 32 + 255) / 256, 256>>>(h, as2, ad2, as_, ad_, N, 4);
    gat_agg_kernel<4, true><<<agg_blocks, 256>>>(h, as_, ad_, b2, bn2g, bn2b, bn2m, bn2v, x1, N);

    // ---- GAT layer 3 (heads=1, concat) ----
    launch_gemm(x1, W3, nullptr, h, N, 128, 128, 0);
    alpha_kernel<<<(N * 32 + 255) / 256, 256>>>(h, as3, ad3, as_, ad_, N, 1);
    gat_agg_kernel<1, false><<<agg_blocks, 256>>>(h, as_, ad_, b3, nullptr, nullptr, nullptr, nullptr, x2, N);

    // ---- classifier MLP ----
    launch_gemm(x2, l1w, l1b, x0, N, 128, 128, 1);   // relu
    launch_gemm(x0, l2w, l2b, m2, N, 64, 128, 1);    // relu
    launch_gemm(m2, l3w, l3b, (float*)d_out, N, 64, 64, 2); // sigmoid
}

// round 11
// speedup vs baseline: 5.5013x; 1.4371x over previous
#include <cuda_runtime.h>
#include <cuda_bf16.h>
#include <math.h>
#include <stdint.h>

#define N_NODES 20000
#define E_MAX   320000

// ---------------- device scratch ----------------------------------------------
__device__ float g_h  [N_NODES * 512];
__device__ float g_x0 [N_NODES * 128];
__device__ float g_x1 [N_NODES * 128];
__device__ float g_x2 [N_NODES * 128];
__device__ float g_as [N_NODES * 4];
__device__ float g_ad [N_NODES * 4];
__device__ float g_m2 [N_NODES * 64];
__device__ int   g_deg[N_NODES];
__device__ int   g_off[N_NODES + 1];
__device__ int   g_cur[N_NODES];
__device__ int   g_csr[E_MAX];
__device__ __nv_bfloat16 g_ah[N_NODES * 256];   // split-bf16 activations (hi)
__device__ __nv_bfloat16 g_al[N_NODES * 256];   // split-bf16 activations (lo)
__device__ __nv_bfloat16 g_bh[512 * 256];       // split-bf16 transposed weights (hi)
__device__ __nv_bfloat16 g_bl[512 * 256];       // split-bf16 transposed weights (lo)

// ---------------- warp MMA helpers (baseline PTX: ldmatrix + mma.sync) --------
__device__ __forceinline__ uint32_t smem_u32(const void* p) {
    uint32_t a;
    asm("{ .reg .u64 t; cvta.to.shared.u64 t, %1; cvt.u32.u64 %0, t; }" : "=r"(a) : "l"(p));
    return a;
}
__device__ __forceinline__ void ldsm_x4(uint32_t* d, uint32_t addr) {
    asm volatile("ldmatrix.sync.aligned.m8n8.x4.shared.b16 {%0,%1,%2,%3}, [%4];"
                 : "=r"(d[0]), "=r"(d[1]), "=r"(d[2]), "=r"(d[3]) : "r"(addr));
}
__device__ __forceinline__ void ldsm_x2(uint32_t* d, uint32_t addr) {
    asm volatile("ldmatrix.sync.aligned.m8n8.x2.shared.b16 {%0,%1}, [%2];"
                 : "=r"(d[0]), "=r"(d[1]) : "r"(addr));
}
__device__ __forceinline__ void mma_bf16(float* c, const uint32_t* a, const uint32_t* b) {
    asm volatile("mma.sync.aligned.m16n8k16.row.col.f32.bf16.bf16.f32 "
                 "{%0,%1,%2,%3}, {%4,%5,%6,%7}, {%8,%9}, {%0,%1,%2,%3};"
                 : "+f"(c[0]), "+f"(c[1]), "+f"(c[2]), "+f"(c[3])
                 : "r"(a[0]), "r"(a[1]), "r"(a[2]), "r"(a[3]), "r"(b[0]), "r"(b[1]));
}

// ---------------- CSR build ----------------------------------------------------
__global__ void zero_deg_kernel(int N) {
    int i = blockIdx.x * blockDim.x + threadIdx.x;
    if (i < N) g_deg[i] = 0;
}
__global__ void hist_kernel(const int* __restrict__ dst, int E) {
    int i = blockIdx.x * blockDim.x + threadIdx.x;
    if (i < E) atomicAdd(&g_deg[dst[i]], 1);
}
__global__ void scan_kernel(int N) {
    __shared__ int sh[1024];
    int tid = threadIdx.x;
    int per = (N + 1023) >> 10;
    int base = tid * per;
    int sum = 0;
    for (int i = 0; i < per; i++) { int idx = base + i; if (idx < N) sum += g_deg[idx]; }
    sh[tid] = sum;
    __syncthreads();
    for (int off = 1; off < 1024; off <<= 1) {
        int v = (tid >= off) ? sh[tid - off] : 0;
        __syncthreads();
        sh[tid] += v;
        __syncthreads();
    }
    int run = tid ? sh[tid - 1] : 0;
    for (int i = 0; i < per; i++) {
        int idx = base + i;
        if (idx < N) { g_off[idx] = run; g_cur[idx] = run; run += g_deg[idx]; }
    }
    if (tid == 1023) g_off[N] = sh[1023];
}
__global__ void scatter_kernel(const int* __restrict__ src, const int* __restrict__ dst, int E) {
    int i = blockIdx.x * blockDim.x + threadIdx.x;
    if (i < E) {
        int p = atomicAdd(&g_cur[dst[i]], 1);
        g_csr[p] = src[i];
    }
}

// ---------------- split-bf16 conversions ---------------------------------------
__global__ void split_kernel(const float* __restrict__ in, __nv_bfloat16* __restrict__ hi,
                             __nv_bfloat16* __restrict__ lo, int n)
{
    int i = blockIdx.x * blockDim.x + threadIdx.x;
    if (i >= n) return;
    float x = in[i];
    __nv_bfloat16 h = __float2bfloat16(x);
    hi[i] = h;
    lo[i] = __float2bfloat16(x - __bfloat162float(h));
}
// W [K,N] row-major -> Wt hi/lo [N,K]
__global__ void splitT_kernel(const float* __restrict__ W, __nv_bfloat16* __restrict__ hi,
                              __nv_bfloat16* __restrict__ lo, int K, int N)
{
    int i = blockIdx.x * blockDim.x + threadIdx.x;
    if (i >= K * N) return;
    int n = i / K, k = i - n * K;
    float x = W[(size_t)k * N + n];
    __nv_bfloat16 h = __float2bfloat16(x);
    hi[i] = h;
    lo[i] = __float2bfloat16(x - __bfloat162float(h));
}

// ---------------- split-bf16 tensor-core GEMM (mma.sync) -----------------------
// C[M,Ntot] = (Ah+Al)[M,K] @ (Bh+Bl)^T   (B stored [Ntot,K] K-major)
// Block tile 128Mx64Nx64K, 8 warps (4x2), warp tile 32x32.
// act: 0 none, 1 relu, 2 sigmoid
#define GLD 72   // smem row stride in bf16 (144B: rows 16B-aligned, conflict-free LDSM)
__global__ __launch_bounds__(256)
void mma_gemm_kernel(const __nv_bfloat16* __restrict__ Ah, const __nv_bfloat16* __restrict__ Al,
                     const __nv_bfloat16* __restrict__ Bh, const __nv_bfloat16* __restrict__ Bl,
                     const float* __restrict__ bias, float* __restrict__ C,
                     int M, int Ntot, int K, int act)
{
    extern __shared__ __nv_bfloat16 sm[];
    __nv_bfloat16* sAh = sm;                  // 128*GLD
    __nv_bfloat16* sAl = sAh + 128 * GLD;
    __nv_bfloat16* sBh = sAl + 128 * GLD;     // 64*GLD
    __nv_bfloat16* sBl = sBh + 64 * GLD;

    int tid = threadIdx.x, lane = tid & 31, warp = tid >> 5;
    int wm = warp >> 1, wn = warp & 1;        // warp grid 4(M) x 2(N)
    int bm = blockIdx.y * 128, bn = blockIdx.x * 64;

    uint32_t aAh = smem_u32(sAh), aAl = smem_u32(sAl);
    uint32_t aBh = smem_u32(sBh), aBl = smem_u32(sBl);

    float acc[2][4][4];
#pragma unroll
    for (int mt = 0; mt < 2; mt++)
#pragma unroll
        for (int nt = 0; nt < 4; nt++)
#pragma unroll
            for (int q = 0; q < 4; q++) acc[mt][nt][q] = 0.f;

    for (int kc = 0; kc < K; kc += 64) {
        // ---- stage A tile (128 x 64 bf16, hi+lo) ----
        for (int i = tid; i < 2048; i += 256) {            // 2048 uint2 = 128 rows x 16
            int row = i >> 4, seg = (i & 15) << 2;
            int m = bm + row, k = kc + seg;
            uint2 hv = make_uint2(0u, 0u), lv = make_uint2(0u, 0u);
            if (m < M) {
                hv = *(const uint2*)(Ah + (size_t)m * K + k);
                lv = *(const uint2*)(Al + (size_t)m * K + k);
            }
            *(uint2*)&sAh[row * GLD + seg] = hv;
            *(uint2*)&sAl[row * GLD + seg] = lv;
        }
        // ---- stage B tile (64 x 64 bf16, hi+lo) ----
        for (int i = tid; i < 1024; i += 256) {
            int row = i >> 4, seg = (i & 15) << 2;
            int n = bn + row, k = kc + seg;
            *(uint2*)&sBh[row * GLD + seg] = *(const uint2*)(Bh + (size_t)n * K + k);
            *(uint2*)&sBl[row * GLD + seg] = *(const uint2*)(Bl + (size_t)n * K + k);
        }
        __syncthreads();

#pragma unroll
        for (int ks = 0; ks < 64; ks += 16) {
            // A fragments: m16k16 row-major via ldmatrix.x4
            uint32_t ah[2][4], al[2][4];
            int ar = lane & 15, ac = (lane >> 4) << 3;
#pragma unroll
            for (int mt = 0; mt < 2; mt++) {
                uint32_t off = (uint32_t)((wm * 32 + mt * 16 + ar) * GLD + ks + ac) * 2;
                ldsm_x4(ah[mt], aAh + off);
                ldsm_x4(al[mt], aAl + off);
            }
            // B fragments: [n][k] rows via ldmatrix.x2 (non-trans == col-major B frag)
            uint32_t bh[4][2], bl[4][2];
            int br = lane & 7, bc = ((lane >> 3) & 1) << 3;
#pragma unroll
            for (int nt = 0; nt < 4; nt++) {
                uint32_t off = (uint32_t)((wn * 32 + nt * 8 + br) * GLD + ks + bc) * 2;
                ldsm_x2(bh[nt], aBh + off);
                ldsm_x2(bl[nt], aBl + off);
            }
#pragma unroll
            for (int mt = 0; mt < 2; mt++)
#pragma unroll
                for (int nt = 0; nt < 4; nt++) {
                    mma_bf16(acc[mt][nt], ah[mt], bh[nt]);   // hi*hi
                    mma_bf16(acc[mt][nt], ah[mt], bl[nt]);   // hi*lo
                    mma_bf16(acc[mt][nt], al[mt], bh[nt]);   // lo*hi
                }
        }
        __syncthreads();
    }

    // ---- epilogue: c0,c1 -> (row, col..col+1); c2,c3 -> (row+8, ...) ----
    int rb = bm + wm * 32 + (lane >> 2);
    int cb = bn + wn * 32 + ((lane & 3) << 1);
#pragma unroll
    for (int mt = 0; mt < 2; mt++) {
        int r = rb + mt * 16;
#pragma unroll
        for (int nt = 0; nt < 4; nt++) {
            int c = cb + nt * 8;
            float bx = bias ? bias[c] : 0.f, by = bias ? bias[c + 1] : 0.f;
#pragma unroll
            for (int half = 0; half < 2; half++) {
                int rr = r + half * 8;
                if (rr >= M) continue;
                float v0 = acc[mt][nt][half * 2 + 0] + bx;
                float v1 = acc[mt][nt][half * 2 + 1] + by;
                if (act == 1)      { v0 = fmaxf(v0, 0.f); v1 = fmaxf(v1, 0.f); }
                else if (act == 2) { v0 = 1.f / (1.f + expf(-v0)); v1 = 1.f / (1.f + expf(-v1)); }
                *(float2*)(C + (size_t)rr * Ntot + c) = make_float2(v0, v1);
            }
        }
    }
}

// ---------------- attention coefficient precompute ----------------------------
__global__ void alpha_kernel(const float* __restrict__ h, const float* __restrict__ a_src,
                             const float* __restrict__ a_dst, float* __restrict__ as_,
                             float* __restrict__ ad_, int N, int H)
{
    int gw = (blockIdx.x * blockDim.x + threadIdx.x) >> 5;
    int lane = threadIdx.x & 31;
    if (gw >= N * H) return;
    int n = gw / H, hh = gw - n * H;
    const float4* hp = (const float4*)(h + ((size_t)n * H + hh) * 128);
    const float4* sp = (const float4*)(a_src + hh * 128);
    const float4* dp = (const float4*)(a_dst + hh * 128);
    float4 v = hp[lane], sv = sp[lane], dv = dp[lane];
    float s = v.x * sv.x + v.y * sv.y + v.z * sv.z + v.w * sv.w;
    float d = v.x * dv.x + v.y * dv.y + v.z * dv.z + v.w * dv.w;
#pragma unroll
    for (int o = 16; o; o >>= 1) {
        s += __shfl_xor_sync(0xFFFFFFFFu, s, o);
        d += __shfl_xor_sync(0xFFFFFFFFu, d, o);
    }
    if (lane == 0) { as_[n * H + hh] = s; ad_[n * H + hh] = d; }
}

// ---------------- fused GAT aggregation (one warp per dst node) ----------------
template<int H, bool DO_BN>
__global__ void gat_agg_kernel(const float* __restrict__ h,
                               const float* __restrict__ as_, const float* __restrict__ ad_,
                               const float* __restrict__ bias,
                               const float* __restrict__ bg, const float* __restrict__ bb,
                               const float* __restrict__ bm_, const float* __restrict__ bv,
                               float* __restrict__ out, int N)
{
    int d = (blockIdx.x * blockDim.x + threadIdx.x) >> 5;
    int lane = threadIdx.x & 31;
    if (d >= N) return;

    float asd[H], add[H];
    if (H == 4) {
        float4 t = ((const float4*)as_)[d];
        asd[0] = t.x; asd[1] = t.y; asd[2] = t.z; asd[3] = t.w;
        t = ((const float4*)ad_)[d];
        add[0] = t.x; add[1] = t.y; add[2] = t.z; add[3] = t.w;
    } else {
        asd[0] = as_[d]; add[0] = ad_[d];
    }

    float acc[H][4];
    float denl[H];
#pragma unroll
    for (int k = 0; k < H; k++) {
        denl[k] = 0.f;
#pragma unroll
        for (int c = 0; c < 4; c++) acc[k][c] = 0.f;
    }

    int r0 = g_off[d], r1 = g_off[d + 1];
    for (int base = r0; base < r1; base += 32) {
        int e = base + lane;
        int s = 0;
        float ex[H];
        if (e < r1) {
            s = g_csr[e];
            float av[H];
            if (H == 4) {
                float4 t = ((const float4*)as_)[s];
                av[0] = t.x; av[1] = t.y; av[2] = t.z; av[3] = t.w;
            } else av[0] = as_[s];
#pragma unroll
            for (int k = 0; k < H; k++) {
                float v = av[k] + add[k];
                v = v > 0.f ? v : 0.2f * v;
                ex[k] = expf(v);
                denl[k] += ex[k];
            }
        } else {
#pragma unroll
            for (int k = 0; k < H; k++) ex[k] = 0.f;
        }
        int cnt = min(32, r1 - base);
        for (int j = 0; j < cnt; j++) {
            int sj = __shfl_sync(0xFFFFFFFFu, s, j);
            const float4* hp = (const float4*)(h + (size_t)sj * (H * 128));
#pragma unroll
            for (int k = 0; k < H; k++) {
                float exj = __shfl_sync(0xFFFFFFFFu, ex[k], j);
                float4 hv = hp[k * 32 + lane];
                acc[k][0] += exj * hv.x;
                acc[k][1] += exj * hv.y;
                acc[k][2] += exj * hv.z;
                acc[k][3] += exj * hv.w;
            }
        }
    }

    const float4* hpd = (const float4*)(h + (size_t)d * (H * 128));
#pragma unroll
    for (int k = 0; k < H; k++) {
        float v = asd[k] + add[k];
        v = v > 0.f ? v : 0.2f * v;
        float exs = expf(v);
        float4 hv = hpd[k * 32 + lane];
        acc[k][0] += exs * hv.x;
        acc[k][1] += exs * hv.y;
        acc[k][2] += exs * hv.z;
        acc[k][3] += exs * hv.w;
        float dk = denl[k];
#pragma unroll
        for (int o = 16; o; o >>= 1) dk += __shfl_xor_sync(0xFFFFFFFFu, dk, o);
        denl[k] = dk + exs;
    }

    float v0 = 0.f, v1 = 0.f, v2 = 0.f, v3 = 0.f;
#pragma unroll
    for (int k = 0; k < H; k++) {
        float r = 1.f / (denl[k] + 1e-16f);
        v0 += acc[k][0] * r;
        v1 += acc[k][1] * r;
        v2 += acc[k][2] * r;
        v3 += acc[k][3] * r;
    }
    if (H == 4) { v0 *= 0.25f; v1 *= 0.25f; v2 *= 0.25f; v3 *= 0.25f; }

    int c0 = lane * 4;
    float4 bz = *(const float4*)(bias + c0);
    v0 += bz.x; v1 += bz.y; v2 += bz.z; v3 += bz.w;

    float4 o4;
    if (DO_BN) {
        float4 gg = *(const float4*)(bg + c0);
        float4 bb4 = *(const float4*)(bb + c0);
        float4 mm = *(const float4*)(bm_ + c0);
        float4 vv = *(const float4*)(bv + c0);
        o4.x = fmaxf(gg.x * (v0 - mm.x) * rsqrtf(vv.x + 1e-5f) + bb4.x, 0.f);
        o4.y = fmaxf(gg.y * (v1 - mm.y) * rsqrtf(vv.y + 1e-5f) + bb4.y, 0.f);
        o4.z = fmaxf(gg.z * (v2 - mm.z) * rsqrtf(vv.z + 1e-5f) + bb4.z, 0.f);
        o4.w = fmaxf(gg.w * (v3 - mm.w) * rsqrtf(vv.w + 1e-5f) + bb4.w, 0.f);
    } else {
        o4 = make_float4(v0, v1, v2, v3);
    }
    *(float4*)(out + (size_t)d * 128 + c0) = o4;
}

// ---------------- host-side orchestration -------------------------------------
static void launch_split(const float* in, __nv_bfloat16* hi, __nv_bfloat16* lo, int n) {
    split_kernel<<<(n + 255) / 256, 256>>>(in, hi, lo, n);
}
static void launch_splitT(const float* W, __nv_bfloat16* hi, __nv_bfloat16* lo, int K, int N) {
    splitT_kernel<<<(K * N + 255) / 256, 256>>>(W, hi, lo, K, N);
}
static void launch_gemm(const __nv_bfloat16* Ah, const __nv_bfloat16* Al,
                        const __nv_bfloat16* Bh, const __nv_bfloat16* Bl,
                        const float* bias, float* C, int M, int Ntot, int K, int act)
{
    static bool attr_set = false;
    size_t smem = (size_t)(128 + 128 + 64 + 64) * GLD * sizeof(__nv_bfloat16);  // 55296
    if (!attr_set) {
        cudaFuncSetAttribute(mma_gemm_kernel, cudaFuncAttributeMaxDynamicSharedMemorySize,
                             (int)smem);
        attr_set = true;
    }
    dim3 grid(Ntot / 64, (M + 127) / 128);
    mma_gemm_kernel<<<grid, 256, smem>>>(Ah, Al, Bh, Bl, bias, C, M, Ntot, K, act);
}

extern "C" void kernel_launch(void* const* d_in, const int* in_sizes, int n_in,
                              void* d_out, int out_size)
{
    const float* x   = (const float*)d_in[0];
    const int*   ei  = (const int*)  d_in[1];
    const float* W1  = (const float*)d_in[2];
    const float* as1 = (const float*)d_in[3];
    const float* ad1 = (const float*)d_in[4];
    const float* b1  = (const float*)d_in[5];
    const float* W2  = (const float*)d_in[6];
    const float* as2 = (const float*)d_in[7];
    const float* ad2 = (const float*)d_in[8];
    const float* b2  = (const float*)d_in[9];
    const float* W3  = (const float*)d_in[10];
    const float* as3 = (const float*)d_in[11];
    const float* ad3 = (const float*)d_in[12];
    const float* b3  = (const float*)d_in[13];
    const float* bn1g = (const float*)d_in[14];
    const float* bn1b = (const float*)d_in[15];
    const float* bn1m = (const float*)d_in[16];
    const float* bn1v = (const float*)d_in[17];
    const float* bn2g = (const float*)d_in[18];
    const float* bn2b = (const float*)d_in[19];
    const float* bn2m = (const float*)d_in[20];
    const float* bn2v = (const float*)d_in[21];
    const float* l1w = (const float*)d_in[22];
    const float* l1b = (const float*)d_in[23];
    const float* l2w = (const float*)d_in[24];
    const float* l2b = (const float*)d_in[25];
    const float* l3w = (const float*)d_in[26];
    const float* l3b = (const float*)d_in[27];

    const int N = in_sizes[0] / 256;       // 20000
    const int E = in_sizes[1] / 2;         // 320000
    const int* src = ei;
    const int* dst = ei + E;

    float *h, *x0, *x1, *x2, *as_, *ad_, *m2;
    __nv_bfloat16 *ah, *al, *bh, *bl;
    cudaGetSymbolAddress((void**)&h,   g_h);
    cudaGetSymbolAddress((void**)&x0,  g_x0);
    cudaGetSymbolAddress((void**)&x1,  g_x1);
    cudaGetSymbolAddress((void**)&x2,  g_x2);
    cudaGetSymbolAddress((void**)&as_, g_as);
    cudaGetSymbolAddress((void**)&ad_, g_ad);
    cudaGetSymbolAddress((void**)&m2,  g_m2);
    cudaGetSymbolAddress((void**)&ah,  g_ah);
    cudaGetSymbolAddress((void**)&al,  g_al);
    cudaGetSymbolAddress((void**)&bh,  g_bh);
    cudaGetSymbolAddress((void**)&bl,  g_bl);

    // ---- CSR build (dst identical for all 3 layers) ----
    zero_deg_kernel<<<(N + 255) / 256, 256>>>(N);
    hist_kernel<<<(E + 255) / 256, 256>>>(dst, E);
    scan_kernel<<<1, 1024>>>(N);
    scatter_kernel<<<(E + 255) / 256, 256>>>(src, dst, E);

    int agg_blocks = (N * 32 + 255) / 256;

    // ---- GAT layer 1 (heads=4, mean) + BN1 + relu ----
    launch_split(x, ah, al, N * 256);
    launch_splitT(W1, bh, bl, 256, 512);
    launch_gemm(ah, al, bh, bl, nullptr, h, N, 512, 256, 0);
    alpha_kernel<<<(N * 4 * 32 + 255) / 256, 256>>>(h, as1, ad1, as_, ad_, N, 4);
    gat_agg_kernel<4, true><<<agg_blocks, 256>>>(h, as_, ad_, b1, bn1g, bn1b, bn1m, bn1v, x0, N);

    // ---- GAT layer 2 (heads=4, mean) + BN2 + relu ----
    launch_split(x0, ah, al, N * 128);
    launch_splitT(W2, bh, bl, 128, 512);
    launch_gemm(ah, al, bh, bl, nullptr, h, N, 512, 128, 0);
    alpha_kernel<<<(N * 4 * 32 + 255) / 256, 256>>>(h, as2, ad2, as_, ad_, N, 4);
    gat_agg_kernel<4, true><<<agg_blocks, 256>>>(h, as_, ad_, b2, bn2g, bn2b, bn2m, bn2v, x1, N);

    // ---- GAT layer 3 (heads=1, concat) ----
    launch_split(x1, ah, al, N * 128);
    launch_splitT(W3, bh, bl, 128, 128);
    launch_gemm(ah, al, bh, bl, nullptr, h, N, 128, 128, 0);
    alpha_kernel<<<(N * 32 + 255) / 256, 256>>>(h, as3, ad3, as_, ad_, N, 1);
    gat_agg_kernel<1, false><<<agg_blocks, 256>>>(h, as_, ad_, b3, nullptr, nullptr, nullptr, nullptr, x2, N);

    // ---- classifier MLP ----
    launch_split(x2, ah, al, N * 128);
    launch_splitT(l1w, bh, bl, 128, 128);
    launch_gemm(ah, al, bh, bl, l1b, x0, N, 128, 128, 1);            // relu

    launch_split(x0, ah, al, N * 128);
    launch_splitT(l2w, bh, bl, 128, 64);
    launch_gemm(ah, al, bh, bl, l2b, m2, N, 64, 128, 1);             // relu

    launch_split(m2, ah, al, N * 64);
    launch_splitT(l3w, bh, bl, 64, 64);
    launch_gemm(ah, al, bh, bl, l3b, (float*)d_out, N, 64, 64, 2);   // sigmoid
}